// round 15
// baseline (speedup 1.0000x reference)
#include <cuda_runtime.h>
#include <cstdint>

// R15 = R13 (DRAM-wall-bound at ~84.4us wall) with 256-bit stores
// (st.global.cs.v8.f32, sm_100+): each thread owns 2 chunks of 8 consecutive
// floats. Same bytes, half the store transactions -> probe whether write-burst
// granularity buys DRAM scheduler efficiency.

#define THREADS 1024
#define NCHUNK8 2    // N/8/THREADS = 16384/8/1024
#define STAGES 3
#define TMA_SPLIT 4

__device__ unsigned g_ticket;   // zero-initialized at module load
__device__ unsigned g_done;

__global__ __launch_bounds__(THREADS, 1)
void sensory_persistent15(const float* __restrict__ enc,
                          const float* __restrict__ w,
                          const int*   __restrict__ pref,
                          float* __restrict__ out,
                          int B, int N, int F, int fmask)
{
    extern __shared__ __align__(128) unsigned char smem_dyn[];
    __shared__ __align__(8) unsigned long long mbar[STAGES];
    __shared__ float warpsums[THREADS / 32];
    __shared__ int rowids_sm[STAGES];

    const int tid = threadIdx.x;
    const unsigned rowbytes = (unsigned)F * 4u;
    const unsigned qbytes = rowbytes / TMA_SPLIT;

    const uint32_t buf_base = (uint32_t)__cvta_generic_to_shared(smem_dyn);
    const uint32_t bar_base = (uint32_t)__cvta_generic_to_shared(&mbar[0]);

    // ---- tid 0: init mbarriers, then claim+issue first two rows immediately
    // (overlaps the pref/weight preload burst below). Other threads don't
    // touch the barriers until after the __syncthreads below.
    if (tid == 0) {
        #pragma unroll
        for (int s = 0; s < STAGES; ++s)
            asm volatile("mbarrier.init.shared::cta.b64 [%0], 1;"
                         :: "r"(bar_base + 8u * s) : "memory");
        asm volatile("fence.proxy.async.shared::cta;" ::: "memory");
        #pragma unroll
        for (int s = 0; s < 2; ++s) {
            int r = (int)atomicAdd(&g_ticket, 1u);
            rowids_sm[s] = r;
            if (r < B) {
                const uint32_t mb = bar_base + 8u * s;
                const uint32_t bf = buf_base + s * rowbytes;
                const char* src = (const char*)(enc + (size_t)r * (size_t)F);
                asm volatile("mbarrier.arrive.expect_tx.shared::cta.b64 _, [%0], %1;"
                             :: "r"(mb), "r"(rowbytes) : "memory");
                #pragma unroll
                for (int q = 0; q < TMA_SPLIT; ++q) {
                    asm volatile("cp.async.bulk.shared::cta.global.mbarrier::complete_tx::bytes "
                                 "[%0], [%1], %2, [%3];"
                                 :: "r"(bf + q * qbytes), "l"(src + q * qbytes),
                                    "r"(qbytes), "r"(mb) : "memory");
                }
            }
        }
    }

    // ---- preload prefs as packed 2x16-bit byte offsets + weights.
    // Thread t owns float8 chunks {t, t+THREADS}; chunk c covers float4
    // indices {2*(t+c*THREADS), 2*(t+c*THREADS)+1}.
    uint32_t pk[NCHUNK8][4];   // 8 offsets per chunk, packed pairwise
    float4   wv[NCHUNK8][2];
    {
        const int4*   pref4 = (const int4*)pref;
        const float4* w4    = (const float4*)w;
        const int n4 = N >> 2;
        #pragma unroll
        for (int c = 0; c < NCHUNK8; ++c) {
            #pragma unroll
            for (int h = 0; h < 2; ++h) {
                int i4 = 2 * (tid + c * THREADS) + h;
                if (i4 < n4) {
                    int4 p = pref4[i4];
                    uint32_t ox, oy, oz, ow;
                    if (fmask) {
                        ox = (uint32_t)(p.x & fmask) << 2;
                        oy = (uint32_t)(p.y & fmask) << 2;
                        oz = (uint32_t)(p.z & fmask) << 2;
                        ow = (uint32_t)(p.w & fmask) << 2;
                    } else {
                        ox = ((unsigned)p.x % (unsigned)F) << 2;
                        oy = ((unsigned)p.y % (unsigned)F) << 2;
                        oz = ((unsigned)p.z % (unsigned)F) << 2;
                        ow = ((unsigned)p.w % (unsigned)F) << 2;
                    }
                    pk[c][2 * h + 0] = ox | (oy << 16);
                    pk[c][2 * h + 1] = oz | (ow << 16);
                    wv[c][h] = w4[i4];
                } else {
                    pk[c][2 * h + 0] = pk[c][2 * h + 1] = 0;
                    wv[c][h] = make_float4(0.f, 0.f, 0.f, 0.f);
                }
            }
        }
    }

    __syncthreads();   // publishes mbarrier init + rowids_sm to all threads

    int cur = 0, nxt2 = 2;   // nxt2 = (cur + 2) % STAGES
    int par = 0;

    for (;;) {
        const int r = rowids_sm[cur];
        if (r >= B) break;

        // ---- claim + issue refill TMA at TOP of iteration (buffer nxt2 free
        // since before the PREVIOUS iteration's __syncthreads) ----
        if (tid == 0) {
            int r2 = (int)atomicAdd(&g_ticket, 1u);
            rowids_sm[nxt2] = r2;
            if (r2 < B) {
                const uint32_t mb = bar_base + 8u * nxt2;
                const uint32_t bf = buf_base + nxt2 * rowbytes;
                const char* src = (const char*)(enc + (size_t)r2 * (size_t)F);
                asm volatile("mbarrier.arrive.expect_tx.shared::cta.b64 _, [%0], %1;"
                             :: "r"(mb), "r"(rowbytes) : "memory");
                #pragma unroll
                for (int q = 0; q < TMA_SPLIT; ++q) {
                    asm volatile("cp.async.bulk.shared::cta.global.mbarrier::complete_tx::bytes "
                                 "[%0], [%1], %2, [%3];"
                                 :: "r"(bf + q * qbytes), "l"(src + q * qbytes),
                                    "r"(qbytes), "r"(mb) : "memory");
                }
            }
        }

        // ---- wait for current buffer ----
        {
            const uint32_t mb = bar_base + 8u * cur;
            uint32_t done;
            asm volatile("{ .reg .pred p; "
                         "mbarrier.try_wait.parity.acquire.cta.shared::cta.b64 p, [%1], %2; "
                         "selp.b32 %0, 1, 0, p; }"
                         : "=r"(done) : "r"(mb), "r"((uint32_t)par) : "memory");
            if (!done) {
                asm volatile("{ .reg .pred P1; "
                             "WL%=: mbarrier.try_wait.parity.acquire.cta.shared::cta.b64 P1, [%0], %1, 0x989680; "
                             "@P1 bra.uni WD%=; bra.uni WL%=; WD%=: }"
                             :: "r"(mb), "r"((uint32_t)par) : "memory");
            }
        }

        const char* srow = (const char*)smem_dyn + (size_t)cur * rowbytes;

        // ---- gather into registers + local sum ----
        float lsum = 0.0f;
        float vals[NCHUNK8][8];
        #pragma unroll
        for (int c = 0; c < NCHUNK8; ++c) {
            #pragma unroll
            for (int h = 0; h < 2; ++h) {
                float4 ww = wv[c][h];
                float a = *(const float*)(srow + (pk[c][2*h]   & 0xFFFFu)) * ww.x;
                float b = *(const float*)(srow + (pk[c][2*h]   >> 16))     * ww.y;
                float d = *(const float*)(srow + (pk[c][2*h+1] & 0xFFFFu)) * ww.z;
                float e = *(const float*)(srow + (pk[c][2*h+1] >> 16))     * ww.w;
                vals[c][4*h+0] = a; vals[c][4*h+1] = b;
                vals[c][4*h+2] = d; vals[c][4*h+3] = e;
                lsum += (a + b) + (d + e);
            }
        }

        // ---- warp partial sums ----
        #pragma unroll
        for (int off = 16; off > 0; off >>= 1)
            lsum += __shfl_down_sync(0xFFFFFFFFu, lsum, off);
        if ((tid & 31) == 0) warpsums[tid >> 5] = lsum;
        __syncthreads();   // sums visible AND all reads of srow done -> release point

        // ---- butterfly final reduce: 1 LDS + 5 SHFL ----
        float tot = warpsums[tid & 31];   // THREADS/32 == 32 entries
        #pragma unroll
        for (int off = 16; off > 0; off >>= 1)
            tot += __shfl_xor_sync(0xFFFFFFFFu, tot, off);
        const float sub = (0.1f / (float)N) * tot;

        // ---- epilogue: subtract + relu, 256-bit streaming stores ----
        float* outr = out + (size_t)r * (size_t)N;
        #pragma unroll
        for (int c = 0; c < NCHUNK8; ++c) {
            float o0 = fmaxf(vals[c][0] - sub, 0.0f);
            float o1 = fmaxf(vals[c][1] - sub, 0.0f);
            float o2 = fmaxf(vals[c][2] - sub, 0.0f);
            float o3 = fmaxf(vals[c][3] - sub, 0.0f);
            float o4 = fmaxf(vals[c][4] - sub, 0.0f);
            float o5 = fmaxf(vals[c][5] - sub, 0.0f);
            float o6 = fmaxf(vals[c][6] - sub, 0.0f);
            float o7 = fmaxf(vals[c][7] - sub, 0.0f);
            float* p = outr + 8 * (tid + c * THREADS);
            asm volatile("st.global.cs.v8.f32 [%0], {%1,%2,%3,%4,%5,%6,%7,%8};"
                         :: "l"(p), "f"(o0), "f"(o1), "f"(o2), "f"(o3),
                            "f"(o4), "f"(o5), "f"(o6), "f"(o7) : "memory");
        }

        // advance ring
        cur  = (cur == STAGES - 1) ? 0 : cur + 1;
        nxt2 = (nxt2 == STAGES - 1) ? 0 : nxt2 + 1;
        if (cur == 0) par ^= 1;
    }

    // ---- self-reset for the next (graph-replayed) launch ----
    if (tid == 0) {
        __threadfence();
        unsigned d = atomicAdd(&g_done, 1u);
        if (d == gridDim.x - 1u) {
            g_ticket = 0u;
            g_done   = 0u;
            __threadfence();
        }
    }
}

extern "C" void kernel_launch(void* const* d_in, const int* in_sizes, int n_in,
                              void* d_out, int out_size)
{
    const float* enc  = (const float*)d_in[0];
    const float* w    = (const float*)d_in[1];
    const int*   pref = (const int*)d_in[2];
    float*       out  = (float*)d_out;

    const int N = in_sizes[1];
    const int B = out_size / N;
    const int F = (int)((long long)in_sizes[0] / (long long)B);
    const int fmask = ((F & (F - 1)) == 0) ? (F - 1) : 0;

    int dev = 0;
    cudaGetDevice(&dev);
    int sms = 148;
    cudaDeviceGetAttribute(&sms, cudaDevAttrMultiProcessorCount, dev);
    int grid = (B < sms) ? B : sms;

    const int smem = STAGES * F * (int)sizeof(float);
    cudaFuncSetAttribute(sensory_persistent15,
                         cudaFuncAttributeMaxDynamicSharedMemorySize, smem);

    sensory_persistent15<<<grid, THREADS, smem>>>(enc, w, pref, out, B, N, F, fmask);
}